// round 1
// baseline (speedup 1.0000x reference)
#include <cuda_runtime.h>
#include <math.h>

#define K 5
#define L_EFF 10
#define NF 17                 // 15 sym wsc entries + kl_beta term + (-logpdf)
#define THREADS 256
#define NBLK 592
#define LOG2PI_F 1.8378770664093453f

// Scratch: per block [m, S, F[0..16]]
__device__ float g_scratch[NBLK * (NF + 2)];
__device__ float g_prior_inv[K * K];
__device__ float g_ld_prior;

// symmetric index helper (i<=j): row-major packed upper triangle
__host__ __device__ __forceinline__ int pidx(int i, int j) {
    return i * K - (i * (i + 1)) / 2 + j;  // valid for i<=j
}

// ---------------------------------------------------------------------------
// Kernel 0: invert prior covariance (5x5 SPD) once; store prior_inv + logdet
// ---------------------------------------------------------------------------
__global__ void prep_kernel(const float* __restrict__ effect_covar,
                            const int* __restrict__ l_iter) {
    if (threadIdx.x != 0 || blockIdx.x != 0) return;
    const int l = *l_iter;
    const float* Pc = effect_covar + l * K * K;

    float A[K][K];
    for (int i = 0; i < K; i++)
        for (int j = 0; j < K; j++) A[i][j] = Pc[i * K + j];

    float Lm[K][K];
    float ld = 0.0f;
    for (int j = 0; j < K; j++) {
        float s = A[j][j];
        for (int k = 0; k < j; k++) s -= Lm[j][k] * Lm[j][k];
        ld += logf(s);
        float ljj = sqrtf(s);
        Lm[j][j] = ljj;
        float il = 1.0f / ljj;
        for (int i = j + 1; i < K; i++) {
            float t = A[i][j];
            for (int k = 0; k < j; k++) t -= Lm[i][k] * Lm[j][k];
            Lm[i][j] = t * il;
        }
    }
    // invert L (lower triangular)
    float Li[K][K];
    for (int j = 0; j < K; j++) {
        Li[j][j] = 1.0f / Lm[j][j];
        for (int i = j + 1; i < K; i++) {
            float t = 0.0f;
            for (int k = j; k < i; k++) t += Lm[i][k] * Li[k][j];
            Li[i][j] = -t / Lm[i][i];
        }
    }
    // prior_inv = Li^T * Li
    for (int i = 0; i < K; i++)
        for (int j = 0; j < K; j++) {
            float t = 0.0f;
            int lo = i > j ? i : j;
            for (int k = lo; k < K; k++) t += Li[k][i] * Li[k][j];
            g_prior_inv[i * K + j] = t;
        }
    g_ld_prior = ld;
}

// ---------------------------------------------------------------------------
// Kernel 1: per-SNP work + online-softmax weighted accumulation
// ---------------------------------------------------------------------------
__global__ void __launch_bounds__(THREADS)
main_kernel(const float* __restrict__ beta_hat,
            const float* __restrict__ inv_shat2,
            const float* __restrict__ pi,
            int P) {
    // prior_inv (symmetric, packed 15) + ld_prior into registers
    float Pri[15];
#pragma unroll
    for (int i = 0; i < K; i++)
#pragma unroll
        for (int j = i; j < K; j++) Pri[pidx(i, j)] = g_prior_inv[i * K + j];
    const float ld_prior = g_ld_prior;

    float m = -INFINITY, S = 0.0f;
    float F[NF];
#pragma unroll
    for (int j = 0; j < NF; j++) F[j] = 0.0f;

    const int stride = gridDim.x * blockDim.x;
    for (int p = blockIdx.x * blockDim.x + threadIdx.x; p < P; p += stride) {
        float invd[K], b[K];
        const int base25 = p * (K * K);
        const int base5 = p * K;
#pragma unroll
        for (int k = 0; k < K; k++) {
            invd[k] = __ldg(&inv_shat2[base25 + k * (K + 1)]);
            b[k] = __ldg(&beta_hat[base5 + k]);
        }

        // A = prior_inv + diag(invd); Cholesky A = L L^T
        float Lm[K][K];
        float iLd[K];
        float prodS = 1.0f;
#pragma unroll
        for (int j = 0; j < K; j++) {
            float s = Pri[pidx(j, j)] + invd[j];
#pragma unroll
            for (int k = 0; k < j; k++) s -= Lm[j][k] * Lm[j][k];
            prodS *= s;
            float ljj = sqrtf(s);
            Lm[j][j] = ljj;
            float il = 1.0f / ljj;
            iLd[j] = il;
#pragma unroll
            for (int i = j + 1; i < K; i++) {
                float t = Pri[pidx(j, i)];
#pragma unroll
                for (int k = 0; k < j; k++) t -= Lm[i][k] * Lm[j][k];
                Lm[i][j] = t * il;
            }
        }
        const float ldA = logf(prodS);  // logdet(A); ld_post = -ldA

        float r_[K];
#pragma unroll
        for (int k = 0; k < K; k++) r_[k] = b[k] * invd[k];

        // forward solve L y = r
        float y[K];
#pragma unroll
        for (int j = 0; j < K; j++) {
            float t = r_[j];
#pragma unroll
            for (int k = 0; k < j; k++) t -= Lm[j][k] * y[k];
            y[j] = t * iLd[j];
        }
        // backward solve L^T mu = y
        float mu[K];
#pragma unroll
        for (int j = K - 1; j >= 0; j--) {
            float t = y[j];
#pragma unroll
            for (int k = j + 1; k < K; k++) t -= Lm[k][j] * mu[k];
            mu[j] = t * iLd[j];
        }
        float maha = 0.0f;
#pragma unroll
        for (int k = 0; k < K; k++) maha += mu[k] * r_[k];

        // Linv (lower)
        float Li[K][K];
#pragma unroll
        for (int j = 0; j < K; j++) {
            Li[j][j] = iLd[j];
#pragma unroll
            for (int i = j + 1; i < K; i++) {
                float t = 0.0f;
#pragma unroll
                for (int k = j; k < i; k++) t += Lm[i][k] * Li[k][j];
                Li[i][j] = -t * iLd[i];
            }
        }
        // Sigma = Li^T Li  (post_covar), packed sym; trace(prior_inv * Sigma)
        float Sg[15];
        float tr = 0.0f;
#pragma unroll
        for (int i = 0; i < K; i++) {
#pragma unroll
            for (int j = i; j < K; j++) {
                float t = 0.0f;
#pragma unroll
                for (int k = j; k < K; k++) t += Li[k][i] * Li[k][j];
                Sg[pidx(i, j)] = t;
                tr += (i == j) ? Pri[pidx(i, j)] * t : 2.0f * Pri[pidx(i, j)] * t;
            }
        }

        // p2 = mu^T prior_inv mu
        float p2 = 0.0f;
#pragma unroll
        for (int i = 0; i < K; i++) {
            float t = 0.0f;
#pragma unroll
            for (int j = 0; j < K; j++) {
                float pv = (i <= j) ? Pri[pidx(i, j)] : Pri[pidx(j, i)];
                t += pv * mu[j];
            }
            p2 += mu[i] * t;
        }

        const float p1 = tr - (float)K;
        const float p3 = ld_prior + ldA;
        const float tkl = 0.5f * (p1 + p2 + p3);
        const float nlp = 0.5f * ((float)K * LOG2PI_F - ldA + maha);  // -logpdf
        const float z = logf(__ldg(&pi[p])) + nlp;

        float f[NF];
#pragma unroll
        for (int i = 0; i < K; i++)
#pragma unroll
            for (int j = i; j < K; j++) f[pidx(i, j)] = Sg[pidx(i, j)] + mu[i] * mu[j];
        f[15] = tkl;
        f[16] = nlp;

        // online softmax accumulate
        if (z > m) {
            float sc = expf(m - z);  // exp(-inf)=0 on first item
            S = S * sc + 1.0f;
#pragma unroll
            for (int j = 0; j < NF; j++) F[j] = F[j] * sc + f[j];
            m = z;
        } else {
            float w = expf(z - m);
            S += w;
#pragma unroll
            for (int j = 0; j < NF; j++) F[j] += w * f[j];
        }
    }

    // ---- block reduction ----
    __shared__ float sm_m[THREADS];
    __shared__ float sred[THREADS][NF + 1];

    const int tid = threadIdx.x;
    sm_m[tid] = m;
    __syncthreads();
    for (int st = THREADS / 2; st > 0; st >>= 1) {
        if (tid < st) sm_m[tid] = fmaxf(sm_m[tid], sm_m[tid + st]);
        __syncthreads();
    }
    const float Mb = sm_m[0];
    __syncthreads();

    float w = (m > -INFINITY && Mb > -INFINITY) ? expf(m - Mb) : 0.0f;
    sred[tid][0] = S * w;
#pragma unroll
    for (int j = 0; j < NF; j++) sred[tid][1 + j] = F[j] * w;
    __syncthreads();
    for (int st = THREADS / 2; st > 0; st >>= 1) {
        if (tid < st) {
#pragma unroll
            for (int j = 0; j < NF + 1; j++) sred[tid][j] += sred[tid + st][j];
        }
        __syncthreads();
    }
    if (tid == 0) {
        float* dst = &g_scratch[blockIdx.x * (NF + 2)];
        dst[0] = Mb;
        dst[1] = sred[0][0];
#pragma unroll
        for (int j = 0; j < NF; j++) dst[2 + j] = sred[0][1 + j];
    }
}

// ---------------------------------------------------------------------------
// Kernel 2: merge block partials, compute outputs
// ---------------------------------------------------------------------------
__global__ void finalize_kernel(const float* __restrict__ effect_covar,
                                const int* __restrict__ l_iter,
                                float* __restrict__ out, int out_size) {
    const int tid = threadIdx.x;
    __shared__ float smax[THREADS];
    __shared__ double sD[THREADS];
    __shared__ double tot[NF + 1];
    __shared__ float res[K * K];
    __shared__ float kl_sh;

    // global max
    float lm = -INFINITY;
    for (int b = tid; b < NBLK; b += THREADS) lm = fmaxf(lm, g_scratch[b * (NF + 2)]);
    smax[tid] = lm;
    __syncthreads();
    for (int st = THREADS / 2; st > 0; st >>= 1) {
        if (tid < st) smax[tid] = fmaxf(smax[tid], smax[tid + st]);
        __syncthreads();
    }
    const float M = smax[0];
    __syncthreads();

    double acc[NF + 1];
#pragma unroll
    for (int j = 0; j < NF + 1; j++) acc[j] = 0.0;
    for (int b = tid; b < NBLK; b += THREADS) {
        const float* sc = &g_scratch[b * (NF + 2)];
        double w = exp((double)(sc[0] - M));
        acc[0] += w * (double)sc[1];
#pragma unroll
        for (int j = 0; j < NF; j++) acc[1 + j] += w * (double)sc[2 + j];
    }
#pragma unroll
    for (int j = 0; j < NF + 1; j++) {
        sD[tid] = acc[j];
        __syncthreads();
        for (int st = THREADS / 2; st > 0; st >>= 1) {
            if (tid < st) sD[tid] += sD[tid + st];
            __syncthreads();
        }
        if (tid == 0) tot[j] = sD[0];
        __syncthreads();
    }

    if (tid == 0) {
        double Stot = tot[0];
        double lse = (double)M + log(Stot);
        int idx = 0;
        for (int i = 0; i < K; i++)
            for (int j = i; j < K; j++) {
                float v = (float)(tot[1 + idx] / Stot);
                res[i * K + j] = v;
                res[j * K + i] = v;
                idx++;
            }
        double klb = tot[1 + 15] / Stot;
        double kla = tot[1 + 16] / Stot - lse;
        kl_sh = (float)(kla + klb);
    }
    __syncthreads();

    const int n_eff = out_size - 1;  // 250 expected
    for (int i = tid; i < n_eff; i += THREADS) out[i] = effect_covar[i];
    __syncthreads();
    const int l = *l_iter;
    if (tid < K * K) out[l * K * K + tid] = res[tid];
    if (tid == 0) out[out_size - 1] = kl_sh;
}

// ---------------------------------------------------------------------------
extern "C" void kernel_launch(void* const* d_in, const int* in_sizes, int n_in,
                              void* d_out, int out_size) {
    const float* beta_hat = (const float*)d_in[0];
    // d_in[1] = shat2 (unused: diagonal, inv available)
    const float* inv_shat2 = (const float*)d_in[2];
    const float* pi = (const float*)d_in[3];
    const float* effect_covar = (const float*)d_in[4];
    const int* l_iter = (const int*)d_in[5];
    float* out = (float*)d_out;

    const int P = in_sizes[0] / K;

    prep_kernel<<<1, 1>>>(effect_covar, l_iter);
    main_kernel<<<NBLK, THREADS>>>(beta_hat, inv_shat2, pi, P);
    finalize_kernel<<<1, THREADS>>>(effect_covar, l_iter, out, out_size);
}

// round 3
// speedup vs baseline: 1.4610x; 1.4610x over previous
#include <cuda_runtime.h>
#include <math.h>

#define K 5
#define NF 17                 // 15 sym wsc entries + kl_beta term + (-logpdf)
#define THREADS 256
#define NBLK 592
#define LOG2PI_F 1.8378770664093453f

// per-block partials: [m, S, F[0..16]]
__device__ float g_scratch[NBLK * (NF + 2)];
__device__ int g_count = 0;

// packed upper-tri index (i<=j)
__device__ __forceinline__ int pidx(int i, int j) {
    return i * K - (i * (i + 1)) / 2 + j;
}
// packed strict-lower index (i>j)
__device__ __forceinline__ int lidx(int i, int j) {
    return i * (i - 1) / 2 + j;
}

__global__ void __launch_bounds__(THREADS)
fused_kernel(const float* __restrict__ beta_hat,
             const float* __restrict__ inv_shat2,
             const float* __restrict__ pi,
             const float* __restrict__ effect_covar,
             const int* __restrict__ l_iter,
             float* __restrict__ out, int out_size, int P) {
    __shared__ float sPri[15];
    __shared__ float sLdPrior;
    __shared__ float wmaxs[8];
    __shared__ float wf[8][NF + 1];
    __shared__ double dws[8][NF + 1];
    __shared__ float res[K * K];
    __shared__ float klsh;
    __shared__ int isLast;

    const int tid = threadIdx.x;
    const int lane = tid & 31;
    const int wid = tid >> 5;

    // ---- per-block prior inversion (thread 0) ----
    if (tid == 0) {
        const int l = *l_iter;
        const float* Pc = effect_covar + l * K * K;
        float A[K][K], Lm[K][K], Li[K][K];
        for (int i = 0; i < K; i++)
            for (int j = 0; j < K; j++) A[i][j] = Pc[i * K + j];
        float ld = 0.0f;
        for (int j = 0; j < K; j++) {
            float s = A[j][j];
            for (int k = 0; k < j; k++) s -= Lm[j][k] * Lm[j][k];
            ld += __logf(s);
            float il = rsqrtf(s);
            Lm[j][j] = s * il;
            for (int i = j + 1; i < K; i++) {
                float t = A[i][j];
                for (int k = 0; k < j; k++) t -= Lm[i][k] * Lm[j][k];
                Lm[i][j] = t * il;
            }
        }
        for (int j = 0; j < K; j++) {
            Li[j][j] = 1.0f / Lm[j][j];
            for (int i = j + 1; i < K; i++) {
                float t = 0.0f;
                for (int k = j; k < i; k++) t += Lm[i][k] * Li[k][j];
                Li[i][j] = -t / Lm[i][i];
            }
        }
        for (int i = 0; i < K; i++)
            for (int j = i; j < K; j++) {
                float t = 0.0f;
                for (int k = j; k < K; k++) t += Li[k][i] * Li[k][j];
                sPri[pidx(i, j)] = t;
            }
        sLdPrior = ld;
    }
    __syncthreads();

    float Pri[15];
#pragma unroll
    for (int q = 0; q < 15; q++) Pri[q] = sPri[q];
    const float ld_prior = sLdPrior;

    // ---- main per-SNP loop ----
    float m = -1e30f, S = 0.0f;
    float F[NF];
#pragma unroll
    for (int j = 0; j < NF; j++) F[j] = 0.0f;

    const int stride = gridDim.x * blockDim.x;
    for (int p = blockIdx.x * blockDim.x + tid; p < P; p += stride) {
        float invd[K], b[K];
        const int base25 = p * (K * K);
        const int base5 = p * K;
#pragma unroll
        for (int k = 0; k < K; k++) {
            invd[k] = __ldg(&inv_shat2[base25 + k * (K + 1)]);
            b[k] = __ldg(&beta_hat[base5 + k]);
        }

        // A = prior_inv + diag(invd); Cholesky (store strict-lower + inv-diag)
        float Loff[10], iLd[K];
        float prodS = 1.0f;
#pragma unroll
        for (int j = 0; j < K; j++) {
            float s = Pri[pidx(j, j)] + invd[j];
#pragma unroll
            for (int k = 0; k < j; k++) s -= Loff[lidx(j, k)] * Loff[lidx(j, k)];
            prodS *= s;
            const float il = rsqrtf(s);
            iLd[j] = il;
#pragma unroll
            for (int i = j + 1; i < K; i++) {
                float t = Pri[pidx(j, i)];
#pragma unroll
                for (int k = 0; k < j; k++) t -= Loff[lidx(i, k)] * Loff[lidx(j, k)];
                Loff[lidx(i, j)] = t * il;
            }
        }
        const float ldA = __logf(prodS);  // logdet(A); ld_post = -ldA

        // r = b .* invd  (overwrite b)
#pragma unroll
        for (int k = 0; k < K; k++) b[k] *= invd[k];

        // forward solve L y = r, then backward L^T mu = y (in place over y)
        float y[K];
#pragma unroll
        for (int j = 0; j < K; j++) {
            float t = b[j];
#pragma unroll
            for (int k = 0; k < j; k++) t -= Loff[lidx(j, k)] * y[k];
            y[j] = t * iLd[j];
        }
#pragma unroll
        for (int j = K - 1; j >= 0; j--) {
            float t = y[j];
#pragma unroll
            for (int k = j + 1; k < K; k++) t -= Loff[lidx(k, j)] * y[k];
            y[j] = t * iLd[j];
        }
        // y now holds mu
        float maha = 0.0f;
#pragma unroll
        for (int k = 0; k < K; k++) maha += y[k] * b[k];

        // in-place invert L: Loff becomes strict-lower of L^-1, diag = iLd
#pragma unroll
        for (int j = 0; j < K; j++) {
#pragma unroll
            for (int i = j + 1; i < K; i++) {
                float t = Loff[lidx(i, j)] * iLd[j];
#pragma unroll
                for (int k = j + 1; k < i; k++) t += Loff[lidx(i, k)] * Loff[lidx(k, j)];
                Loff[lidx(i, j)] = -t * iLd[i];
            }
        }

        // Sigma = Li^T Li (packed upper), trace(prior_inv * Sigma)
        float Sg[15];
        float tr = 0.0f;
#pragma unroll
        for (int i = 0; i < K; i++) {
#pragma unroll
            for (int j = i; j < K; j++) {
                float t = 0.0f;
#pragma unroll
                for (int k = j; k < K; k++) {
                    const float lki = (k == i) ? iLd[i] : Loff[lidx(k, i)];
                    const float lkj = (k == j) ? iLd[j] : Loff[lidx(k, j)];
                    t += lki * lkj;
                }
                Sg[pidx(i, j)] = t;
                tr += (i == j) ? Pri[pidx(i, j)] * t : 2.0f * Pri[pidx(i, j)] * t;
            }
        }

        // p2 = mu^T prior_inv mu
        float p2 = 0.0f;
#pragma unroll
        for (int i = 0; i < K; i++) {
            float t = 0.0f;
#pragma unroll
            for (int j = 0; j < K; j++) {
                const float pv = (i <= j) ? Pri[pidx(i, j)] : Pri[pidx(j, i)];
                t += pv * y[j];
            }
            p2 += y[i] * t;
        }

        const float tkl = 0.5f * (tr - (float)K + p2 + ld_prior + ldA);
        const float nlp = 0.5f * ((float)K * LOG2PI_F - ldA + maha);  // -logpdf
        const float z = __logf(__ldg(&pi[p])) + nlp;

        // branch-free online softmax accumulate
        const float newm = fmaxf(m, z);
        const float sc = __expf(m - newm);
        const float w = __expf(z - newm);
        S = S * sc + w;
#pragma unroll
        for (int i = 0; i < K; i++)
#pragma unroll
            for (int j = i; j < K; j++) {
                const int q = pidx(i, j);
                F[q] = F[q] * sc + w * (Sg[q] + y[i] * y[j]);
            }
        F[15] = F[15] * sc + w * tkl;
        F[16] = F[16] * sc + w * nlp;
        m = newm;
    }

    // ---- block reduction: max via shuffle ----
    float bm = m;
#pragma unroll
    for (int o = 16; o; o >>= 1) bm = fmaxf(bm, __shfl_xor_sync(0xFFFFFFFFu, bm, o));
    if (lane == 0) wmaxs[wid] = bm;
    __syncthreads();
    float Mb = wmaxs[0];
#pragma unroll
    for (int q = 1; q < 8; q++) Mb = fmaxf(Mb, wmaxs[q]);

    const float w0 = __expf(m - Mb);
    float vals[NF + 1];
    vals[0] = S * w0;
#pragma unroll
    for (int j = 0; j < NF; j++) vals[1 + j] = F[j] * w0;
#pragma unroll
    for (int j = 0; j < NF + 1; j++) {
#pragma unroll
        for (int o = 16; o; o >>= 1) vals[j] += __shfl_xor_sync(0xFFFFFFFFu, vals[j], o);
    }
    if (lane == 0) {
#pragma unroll
        for (int j = 0; j < NF + 1; j++) wf[wid][j] = vals[j];
    }
    __syncthreads();
    if (wid == 0) {
        float acc[NF + 1];
#pragma unroll
        for (int j = 0; j < NF + 1; j++) acc[j] = (lane < 8) ? wf[lane][j] : 0.0f;
#pragma unroll
        for (int j = 0; j < NF + 1; j++) {
#pragma unroll
            for (int o = 4; o; o >>= 1) acc[j] += __shfl_xor_sync(0xFFFFFFFFu, acc[j], o);
        }
        if (lane == 0) {
            float* dst = &g_scratch[blockIdx.x * (NF + 2)];
            dst[0] = Mb;
#pragma unroll
            for (int j = 0; j < NF + 1; j++) dst[1 + j] = acc[j];
        }
    }

    // ---- last-block finalize ----
    __threadfence();
    if (tid == 0) {
        const int old = atomicAdd(&g_count, 1);
        isLast = (old == (int)gridDim.x - 1) ? 1 : 0;
    }
    __syncthreads();
    if (!isLast) return;
    __threadfence();

    // global max over block partials
    float lm = -1e30f;
    for (int b2 = tid; b2 < NBLK; b2 += THREADS) lm = fmaxf(lm, g_scratch[b2 * (NF + 2)]);
#pragma unroll
    for (int o = 16; o; o >>= 1) lm = fmaxf(lm, __shfl_xor_sync(0xFFFFFFFFu, lm, o));
    if (lane == 0) wmaxs[wid] = lm;
    __syncthreads();
    float M = wmaxs[0];
#pragma unroll
    for (int q = 1; q < 8; q++) M = fmaxf(M, wmaxs[q]);

    double acc[NF + 1];
#pragma unroll
    for (int j = 0; j < NF + 1; j++) acc[j] = 0.0;
    for (int b2 = tid; b2 < NBLK; b2 += THREADS) {
        const float* sc2 = &g_scratch[b2 * (NF + 2)];
        const double wgt = exp((double)(sc2[0] - M));
        acc[0] += wgt * (double)sc2[1];
#pragma unroll
        for (int j = 0; j < NF; j++) acc[1 + j] += wgt * (double)sc2[2 + j];
    }
#pragma unroll
    for (int j = 0; j < NF + 1; j++) {
#pragma unroll
        for (int o = 16; o; o >>= 1) acc[j] += __shfl_xor_sync(0xFFFFFFFFu, acc[j], o);
    }
    if (lane == 0) {
#pragma unroll
        for (int j = 0; j < NF + 1; j++) dws[wid][j] = acc[j];
    }
    __syncthreads();
    if (tid == 0) {
        double tot[NF + 1];
#pragma unroll
        for (int j = 0; j < NF + 1; j++) {
            double t = 0.0;
            for (int q = 0; q < 8; q++) t += dws[q][j];
            tot[j] = t;
        }
        const double Stot = tot[0];
        const double lse = (double)M + log(Stot);
        int idx = 0;
        for (int i = 0; i < K; i++)
            for (int j = i; j < K; j++) {
                const float v = (float)(tot[1 + idx] / Stot);
                res[i * K + j] = v;
                res[j * K + i] = v;
                idx++;
            }
        const double klb = tot[1 + 15] / Stot;
        const double kla = tot[1 + 16] / Stot - lse;
        klsh = (float)(kla + klb);
    }
    __syncthreads();

    const int n_eff = out_size - 1;
    for (int i = tid; i < n_eff; i += THREADS) out[i] = effect_covar[i];
    __syncthreads();
    const int l = *l_iter;
    if (tid < K * K) out[l * K * K + tid] = res[tid];
    if (tid == 0) {
        out[out_size - 1] = klsh;
        g_count = 0;  // reset for next graph replay
    }
}

// ---------------------------------------------------------------------------
extern "C" void kernel_launch(void* const* d_in, const int* in_sizes, int n_in,
                              void* d_out, int out_size) {
    const float* beta_hat = (const float*)d_in[0];
    // d_in[1] = shat2 (unused: diagonal, inverse available)
    const float* inv_shat2 = (const float*)d_in[2];
    const float* pi = (const float*)d_in[3];
    const float* effect_covar = (const float*)d_in[4];
    const int* l_iter = (const int*)d_in[5];
    float* out = (float*)d_out;

    const int P = in_sizes[0] / K;

    fused_kernel<<<NBLK, THREADS>>>(beta_hat, inv_shat2, pi, effect_covar,
                                    l_iter, out, out_size, P);
}

// round 5
// speedup vs baseline: 1.6926x; 1.1586x over previous
#include <cuda_runtime.h>
#include <math.h>

#define K 5
#define NF 17                 // 15 sym wsc entries + kl_beta term + (-logpdf)
#define THREADS 256
#define TILE 256
#define NBLK 592
#define LOG2PI_F 1.8378770664093453f

// per-block partials: [m, S, F[0..16]]
__device__ float g_scratch[NBLK * (NF + 2)];
__device__ int g_count = 0;

// packed upper-tri index (i<=j)
__device__ __forceinline__ int pidx(int i, int j) {
    return i * K - (i * (i + 1)) / 2 + j;
}
// packed strict-lower index (i>j)
__device__ __forceinline__ int lidx(int i, int j) {
    return i * (i - 1) / 2 + j;
}

__global__ void __launch_bounds__(THREADS)
fused_kernel(const float* __restrict__ beta_hat,
             const float* __restrict__ inv_shat2,
             const float* __restrict__ pi,
             const float* __restrict__ effect_covar,
             const int* __restrict__ l_iter,
             float* __restrict__ out, int out_size, int P) {
    __shared__ float sInv[TILE * 25];    // 25600 B
    __shared__ float sBeta[TILE * 5];    // 5120 B
    __shared__ float sPri[15];
    __shared__ float sLdPrior;
    __shared__ float wmaxs[8];
    __shared__ float wf[8][NF + 1];
    __shared__ double dws[8][NF + 1];
    __shared__ float res[K * K];
    __shared__ float klsh;
    __shared__ int isLast;

    const int tid = threadIdx.x;
    const int lane = tid & 31;
    const int wid = tid >> 5;

    // ---- per-block prior inversion (thread 0) ----
    if (tid == 0) {
        const int l = *l_iter;
        const float* Pc = effect_covar + l * K * K;
        float A[K][K], Lm[K][K], Li[K][K];
        for (int i = 0; i < K; i++)
            for (int j = 0; j < K; j++) A[i][j] = Pc[i * K + j];
        float ld = 0.0f;
        for (int j = 0; j < K; j++) {
            float s = A[j][j];
            for (int k = 0; k < j; k++) s -= Lm[j][k] * Lm[j][k];
            ld += __logf(s);
            float il = rsqrtf(s);
            Lm[j][j] = s * il;
            for (int i = j + 1; i < K; i++) {
                float t = A[i][j];
                for (int k = 0; k < j; k++) t -= Lm[i][k] * Lm[j][k];
                Lm[i][j] = t * il;
            }
        }
        for (int j = 0; j < K; j++) {
            Li[j][j] = 1.0f / Lm[j][j];
            for (int i = j + 1; i < K; i++) {
                float t = 0.0f;
                for (int k = j; k < i; k++) t += Lm[i][k] * Li[k][j];
                Li[i][j] = -t / Lm[i][i];
            }
        }
        for (int i = 0; i < K; i++)
            for (int j = i; j < K; j++) {
                float t = 0.0f;
                for (int k = j; k < K; k++) t += Li[k][i] * Li[k][j];
                sPri[pidx(i, j)] = t;
            }
        sLdPrior = ld;
    }
    __syncthreads();

    const float ld_prior = sLdPrior;

    // ---- per-thread accumulators ----
    float m = -1e30f, S = 0.0f;
    float F[NF];
#pragma unroll
    for (int j = 0; j < NF; j++) F[j] = 0.0f;

    const int ntiles = (P + TILE - 1) / TILE;
    const int invTotalF = P * 25;
    const int invTotal4 = invTotalF >> 2;
    const int betaTotalF = P * 5;
    const int betaTotal4 = betaTotalF >> 2;
    const float4* __restrict__ inv4 = (const float4*)inv_shat2;
    const float4* __restrict__ beta4 = (const float4*)beta_hat;
    float4* sInv4 = (float4*)sInv;
    float4* sBeta4 = (float4*)sBeta;

    for (int tile = blockIdx.x; tile < ntiles; tile += gridDim.x) {
        // ---- coalesced stage: inv_shat2 tile (1600 float4) ----
        const int invBase4 = tile * (TILE * 25 / 4);     // 1600 per tile
#pragma unroll
        for (int i = 0; i < 7; i++) {
            const int idx = i * THREADS + tid;
            const int g4 = invBase4 + idx;
            if (idx < TILE * 25 / 4 && g4 < invTotal4) sInv4[idx] = inv4[g4];
        }
        // ---- coalesced stage: beta tile (320 float4) — needs 2 iterations ----
        const int betaBase4 = tile * (TILE * 5 / 4);     // 320 per tile
#pragma unroll
        for (int i = 0; i < 2; i++) {
            const int idx = i * THREADS + tid;
            const int g4 = betaBase4 + idx;
            if (idx < TILE * 5 / 4 && g4 < betaTotal4) sBeta4[idx] = beta4[g4];
        }
        // scalar remainder (empty when totals are multiples of 4)
        for (int f = (invTotal4 << 2) + tid; f < invTotalF; f += THREADS) {
            const int local = f - tile * (TILE * 25);
            if (local >= 0 && local < TILE * 25) sInv[local] = inv_shat2[f];
        }
        for (int f = (betaTotal4 << 2) + tid; f < betaTotalF; f += THREADS) {
            const int local = f - tile * (TILE * 5);
            if (local >= 0 && local < TILE * 5) sBeta[local] = beta_hat[f];
        }
        __syncthreads();

        const int p = tile * TILE + tid;
        if (p < P) {
            float invd[K], b[K];
#pragma unroll
            for (int k = 0; k < K; k++) {
                invd[k] = sInv[tid * 25 + k * 6];
                b[k] = sBeta[tid * 5 + k];
            }

            // A = prior_inv + diag(invd); Cholesky (strict-lower + inv-diag)
            float Loff[10], iLd[K];
            float prodS = 1.0f;
#pragma unroll
            for (int j = 0; j < K; j++) {
                float s = sPri[pidx(j, j)] + invd[j];
#pragma unroll
                for (int k = 0; k < j; k++) s -= Loff[lidx(j, k)] * Loff[lidx(j, k)];
                prodS *= s;
                const float il = rsqrtf(s);
                iLd[j] = il;
#pragma unroll
                for (int i = j + 1; i < K; i++) {
                    float t = sPri[pidx(j, i)];
#pragma unroll
                    for (int k = 0; k < j; k++) t -= Loff[lidx(i, k)] * Loff[lidx(j, k)];
                    Loff[lidx(i, j)] = t * il;
                }
            }
            const float ldA = __logf(prodS);  // logdet(A); ld_post = -ldA

            // r = b .* invd (overwrite b)
#pragma unroll
            for (int k = 0; k < K; k++) b[k] *= invd[k];

            // forward L y = r; backward L^T mu = y (in place)
            float y[K];
#pragma unroll
            for (int j = 0; j < K; j++) {
                float t = b[j];
#pragma unroll
                for (int k = 0; k < j; k++) t -= Loff[lidx(j, k)] * y[k];
                y[j] = t * iLd[j];
            }
#pragma unroll
            for (int j = K - 1; j >= 0; j--) {
                float t = y[j];
#pragma unroll
                for (int k = j + 1; k < K; k++) t -= Loff[lidx(k, j)] * y[k];
                y[j] = t * iLd[j];
            }
            float maha = 0.0f;
#pragma unroll
            for (int k = 0; k < K; k++) maha += y[k] * b[k];

            // in-place invert L
#pragma unroll
            for (int j = 0; j < K; j++) {
#pragma unroll
                for (int i = j + 1; i < K; i++) {
                    float t = Loff[lidx(i, j)] * iLd[j];
#pragma unroll
                    for (int k = j + 1; k < i; k++) t += Loff[lidx(i, k)] * Loff[lidx(k, j)];
                    Loff[lidx(i, j)] = -t * iLd[i];
                }
            }

            // features: f[q] = Sigma_q + mu_i*mu_j (Sigma = Li^T Li)
            float fq[15];
#pragma unroll
            for (int i = 0; i < K; i++) {
#pragma unroll
                for (int j = i; j < K; j++) {
                    float t = y[i] * y[j];
#pragma unroll
                    for (int k = j; k < K; k++) {
                        const float lki = (k == i) ? iLd[i] : Loff[lidx(k, i)];
                        const float lkj = (k == j) ? iLd[j] : Loff[lidx(k, j)];
                        t += lki * lkj;
                    }
                    fq[pidx(i, j)] = t;
                }
            }

            // tkl = 0.5*(maha + ld_prior + ldA - sum_k invd_k * fdiag_k)
            float dsum = invd[0] * fq[0] + invd[1] * fq[5] + invd[2] * fq[9] +
                         invd[3] * fq[12] + invd[4] * fq[14];
            const float tkl = 0.5f * (maha + ld_prior + ldA - dsum);
            const float nlp = 0.5f * ((float)K * LOG2PI_F - ldA + maha);  // -logpdf
            const float z = __logf(pi[p]) + nlp;

            // online softmax accumulate (branchy: rescale path is rare)
            if (z <= m) {
                const float w = __expf(z - m);
                S += w;
#pragma unroll
                for (int q = 0; q < 15; q++) F[q] += w * fq[q];
                F[15] += w * tkl;
                F[16] += w * nlp;
            } else {
                const float sc = __expf(m - z);  // 0 on first item
                S = S * sc + 1.0f;
#pragma unroll
                for (int q = 0; q < 15; q++) F[q] = F[q] * sc + fq[q];
                F[15] = F[15] * sc + tkl;
                F[16] = F[16] * sc + nlp;
                m = z;
            }
        }
        __syncthreads();
    }

    // ---- block reduction: max via shuffle ----
    float bm = m;
#pragma unroll
    for (int o = 16; o; o >>= 1) bm = fmaxf(bm, __shfl_xor_sync(0xFFFFFFFFu, bm, o));
    if (lane == 0) wmaxs[wid] = bm;
    __syncthreads();
    float Mb = wmaxs[0];
#pragma unroll
    for (int q = 1; q < 8; q++) Mb = fmaxf(Mb, wmaxs[q]);

    const float w0 = __expf(m - Mb);
    float vals[NF + 1];
    vals[0] = S * w0;
#pragma unroll
    for (int j = 0; j < NF; j++) vals[1 + j] = F[j] * w0;
#pragma unroll
    for (int j = 0; j < NF + 1; j++) {
#pragma unroll
        for (int o = 16; o; o >>= 1) vals[j] += __shfl_xor_sync(0xFFFFFFFFu, vals[j], o);
    }
    if (lane == 0) {
#pragma unroll
        for (int j = 0; j < NF + 1; j++) wf[wid][j] = vals[j];
    }
    __syncthreads();
    if (wid == 0) {
        float acc[NF + 1];
#pragma unroll
        for (int j = 0; j < NF + 1; j++) acc[j] = (lane < 8) ? wf[lane][j] : 0.0f;
#pragma unroll
        for (int j = 0; j < NF + 1; j++) {
#pragma unroll
            for (int o = 4; o; o >>= 1) acc[j] += __shfl_xor_sync(0xFFFFFFFFu, acc[j], o);
        }
        if (lane == 0) {
            float* dst = &g_scratch[blockIdx.x * (NF + 2)];
            dst[0] = Mb;
#pragma unroll
            for (int j = 0; j < NF + 1; j++) dst[1 + j] = acc[j];
        }
    }

    // ---- last-block finalize ----
    __threadfence();
    if (tid == 0) {
        const int old = atomicAdd(&g_count, 1);
        isLast = (old == (int)gridDim.x - 1) ? 1 : 0;
    }
    __syncthreads();
    if (!isLast) return;
    __threadfence();

    float lm = -1e30f;
    for (int b2 = tid; b2 < NBLK; b2 += THREADS) lm = fmaxf(lm, g_scratch[b2 * (NF + 2)]);
#pragma unroll
    for (int o = 16; o; o >>= 1) lm = fmaxf(lm, __shfl_xor_sync(0xFFFFFFFFu, lm, o));
    if (lane == 0) wmaxs[wid] = lm;
    __syncthreads();
    float M = wmaxs[0];
#pragma unroll
    for (int q = 1; q < 8; q++) M = fmaxf(M, wmaxs[q]);

    double acc[NF + 1];
#pragma unroll
    for (int j = 0; j < NF + 1; j++) acc[j] = 0.0;
    for (int b2 = tid; b2 < NBLK; b2 += THREADS) {
        const float* sc2 = &g_scratch[b2 * (NF + 2)];
        const double wgt = exp((double)(sc2[0] - M));
        acc[0] += wgt * (double)sc2[1];
#pragma unroll
        for (int j = 0; j < NF; j++) acc[1 + j] += wgt * (double)sc2[2 + j];
    }
#pragma unroll
    for (int j = 0; j < NF + 1; j++) {
#pragma unroll
        for (int o = 16; o; o >>= 1) acc[j] += __shfl_xor_sync(0xFFFFFFFFu, acc[j], o);
    }
    if (lane == 0) {
#pragma unroll
        for (int j = 0; j < NF + 1; j++) dws[wid][j] = acc[j];
    }
    __syncthreads();
    if (tid == 0) {
        double tot[NF + 1];
#pragma unroll
        for (int j = 0; j < NF + 1; j++) {
            double t = 0.0;
            for (int q = 0; q < 8; q++) t += dws[q][j];
            tot[j] = t;
        }
        const double Stot = tot[0];
        const double lse = (double)M + log(Stot);
        int idx = 0;
        for (int i = 0; i < K; i++)
            for (int j = i; j < K; j++) {
                const float v = (float)(tot[1 + idx] / Stot);
                res[i * K + j] = v;
                res[j * K + i] = v;
                idx++;
            }
        const double klb = tot[1 + 15] / Stot;
        const double kla = tot[1 + 16] / Stot - lse;
        klsh = (float)(kla + klb);
    }
    __syncthreads();

    const int n_eff = out_size - 1;
    for (int i = tid; i < n_eff; i += THREADS) out[i] = effect_covar[i];
    __syncthreads();
    const int l = *l_iter;
    if (tid < K * K) out[l * K * K + tid] = res[tid];
    if (tid == 0) {
        out[out_size - 1] = klsh;
        g_count = 0;  // reset for next graph replay
    }
}

// ---------------------------------------------------------------------------
extern "C" void kernel_launch(void* const* d_in, const int* in_sizes, int n_in,
                              void* d_out, int out_size) {
    const float* beta_hat = (const float*)d_in[0];
    // d_in[1] = shat2 (unused: diagonal, inverse available)
    const float* inv_shat2 = (const float*)d_in[2];
    const float* pi = (const float*)d_in[3];
    const float* effect_covar = (const float*)d_in[4];
    const int* l_iter = (const int*)d_in[5];
    float* out = (float*)d_out;

    const int P = in_sizes[0] / K;

    fused_kernel<<<NBLK, THREADS>>>(beta_hat, inv_shat2, pi, effect_covar,
                                    l_iter, out, out_size, P);
}